// round 12
// baseline (speedup 1.0000x reference)
#include <cuda_runtime.h>
#include <cuda_fp16.h>
#include <cuda_bf16.h>
#include <mma.h>
#include <cstdint>

using namespace nvcuda;

// ---------------- problem constants ----------------
#define BB   64
#define CC   768
#define NFINE 196
#define NCOARSE 49
#define KDIM 768
#define N3   2304
#define FINE_ROWS   (BB*NFINE)     // 12544
#define COARSE_ROWS (BB*NCOARSE)   // 3136
#define ALL_ROWS    (FINE_ROWS + COARSE_ROWS)  // 15680

// ---------------- device scratch (static, no allocs) ----------------
__device__ __half g_Ah    [ALL_ROWS*KDIM];     // compact A rows in fp16
__device__ __half g_Wh    [KDIM*CC];           // W_pe in fp16
__device__ float g_pe     [ALL_ROWS*CC];       // only written when g_flag != 0
__device__ float g_tok    [BB*NCOARSE*4*CC];
__device__ float g_qkv    [BB*NCOARSE*4*N3];
__device__ float g_o      [BB*NCOARSE*4*CC];
__device__ float g_po     [BB*NCOARSE*4*CC];
__device__ float g_mean   [BB*NCOARSE*CC];
__device__ float g_z      [BB*NCOARSE*CC];
__device__ int   g_m32    [BB*NCOARSE];
__device__ int   g_finepos[BB*NFINE];
__device__ int   g_coarsepos[BB*NCOARSE];
__device__ int   g_rowsrc [ALL_ROWS];
__device__ int   g_rowdst [ALL_ROWS];
__device__ int   g_rowemb [ALL_ROWS];
__device__ int   g_nsel;
__device__ int   g_seq[BB];
__device__ int   g_cls[BB];
__device__ int   g_total;
__device__ int   g_flag;                        // monotone: set iff zero_w/zero_b nonzero

// ---------------- helpers ----------------
__device__ __forceinline__ uint32_t smem_u32(const void* p)
{
    uint32_t a;
    asm("{ .reg .u64 t; cvta.to.shared.u64 t, %1; cvt.u32.u64 %0, t; }" : "=r"(a) : "l"(p));
    return a;
}
__device__ __forceinline__ void cp_async16(uint32_t dst, const void* src, bool pred)
{
    int sz = pred ? 16 : 0;   // sz=0 -> zero-fill
    asm volatile("cp.async.cg.shared.global [%0], [%1], 16, %2;\n"
                 :: "r"(dst), "l"(src), "r"(sz));
}
__device__ __forceinline__ void cp_commit()  { asm volatile("cp.async.commit_group;\n"); }
__device__ __forceinline__ void cp_wait0()   { asm volatile("cp.async.wait_group 0;\n"); }
__device__ __forceinline__ void cp_wait1()   { asm volatile("cp.async.wait_group 1;\n"); }

// ---------------- prep: flag scan + W_pe -> fp16 ----------------
__global__ void __launch_bounds__(256) prep_kernel(
    const float* __restrict__ zw, const float* __restrict__ zb,
    const float* __restrict__ W)
{
    int nz = 0;
    for (int i = blockIdx.x*blockDim.x + threadIdx.x; i < CC*CC; i += gridDim.x*blockDim.x) {
        nz |= (zw[i] != 0.0f);
        g_Wh[i] = __float2half_rn(W[i]);       // KDIM*CC == CC*CC
    }
    if (blockIdx.x == 0)
        for (int i = threadIdx.x; i < CC; i += blockDim.x) nz |= (zb[i] != 0.0f);
    if (__syncthreads_or(nz) && threadIdx.x == 0) atomicOr(&g_flag, 1);
}

// ---------------- mask / positions / compact row list ----------------
__global__ void __launch_bounds__(128) mask_kernel(
    const float* __restrict__ e, float* __restrict__ out, int out_size)
{
    __shared__ int s_nc[BB];
    __shared__ int s_cls[BB+1];
    __shared__ int s_flagv;
    int t = threadIdx.x;
    if (t == 0) s_flagv = g_flag;
    if (t < BB) {
        int b = t, nc = 0;
        const float* eb = e + b*NFINE;
        for (int cc = 0; cc < NCOARSE; cc++) {
            int ci = cc / 7, cj = cc % 7;
            float m = (eb[(2*ci)*14 + 2*cj]   + eb[(2*ci)*14 + 2*cj+1] +
                       eb[(2*ci+1)*14 + 2*cj] + eb[(2*ci+1)*14 + 2*cj+1]) * 0.25f;
            int sel = m < 0.5f;
            g_m32[b*NCOARSE + cc] = sel;
            nc += sel;
        }
        s_nc[t] = nc;
    }
    __syncthreads();
    if (t == 0) {
        int acc = 0;
        for (int b = 0; b < BB; b++) {
            s_cls[b] = acc;
            g_cls[b] = acc;
            int nc = s_nc[b];
            int seq = 1 + 4*(NCOARSE - nc) + nc;
            g_seq[b] = seq;
            acc += seq;
        }
        g_total = acc;
        s_cls[BB] = acc;
        g_nsel = s_flagv ? ALL_ROWS : (acc - BB);
    }
    __syncthreads();
    int flagv = s_flagv;
    if (t < BB) {
        int b = t;
        int base = s_cls[b];
        int idx  = base - b;
        int rank = 0;
        for (int f = 0; f < NFINE; f++) {
            int i = f / 14, j = f % 14;
            int sel = g_m32[b*NCOARSE + (i>>1)*7 + (j>>1)];
            int pos = sel ? -1 : (base + 1 + rank);
            g_finepos[b*NFINE + f] = pos;
            if (!sel) {
                if (!flagv) {
                    g_rowsrc[idx] = b*NFINE + f;
                    g_rowdst[idx] = pos;
                    g_rowemb[idx] = f;
                }
                idx++; rank++;
            }
        }
        int crank = 0;
        for (int cc = 0; cc < NCOARSE; cc++) {
            int sel = g_m32[b*NCOARSE + cc];
            int pos = sel ? (base + 1 + rank + crank) : -1;
            g_coarsepos[b*NCOARSE + cc] = pos;
            if (sel) {
                if (!flagv) {
                    g_rowsrc[idx] = FINE_ROWS + b*NCOARSE + cc;
                    g_rowdst[idx] = pos;
                    g_rowemb[idx] = NFINE + cc;
                }
                idx++; crank++;
            }
        }
    }
    if (flagv) {
        for (int i = t; i < ALL_ROWS; i += 128) { g_rowsrc[i] = i; g_rowdst[i] = i; }
    }
    __syncthreads();
    long long total = s_cls[BB];
    long long need = total * CC + 2*BB;
    if ((long long)out_size == need && t < BB) {
        out[total*CC + t]      = (float)g_seq[t];
        out[total*CC + BB + t] = (float)g_cls[t];
    }
}

// ---------------- build compact fp16 A matrix + cls rows ----------------
__global__ void __launch_bounds__(256) build_A(
    const float* __restrict__ x, const float* __restrict__ cls_token,
    const float* __restrict__ mini_pos, float* __restrict__ out)
{
    if (blockIdx.x < BB) {
        int pos = g_cls[blockIdx.x];
        float* dst = out + (size_t)pos*CC;
        for (int c = threadIdx.x; c < CC; c += 256) dst[c] = cls_token[c] + mini_pos[c];
    }
    int nsel = g_nsel;
    int total = nsel * (KDIM/4);                 // quads of 4 halfs
    for (int q = blockIdx.x*blockDim.x + threadIdx.x; q < total;
         q += gridDim.x*blockDim.x) {
        int row = q / (KDIM/4);
        int k4  = (q - row*(KDIM/4)) * 4;        // k of first element
        int src = g_rowsrc[row];
        float v0, v1, v2, v3;
        int c  = k4 >> 8;
        int pi = (k4 >> 4) & 15;
        int pj = k4 & 15;
        if (src < FINE_ROWS) {
            int b = src / NFINE;
            int f = src - b*NFINE;
            int i = f / 14, j = f - (f/14)*14;
            const float* p = x + ((size_t)(b*3 + c)*224 + i*16 + pi)*224 + j*16 + pj;
            float4 v = *reinterpret_cast<const float4*>(p);
            v0 = v.x; v1 = v.y; v2 = v.z; v3 = v.w;
        } else {
            int rr = src - FINE_ROWS;
            int b  = rr / NCOARSE;
            int cc = rr - b*NCOARSE;
            int ci = cc / 7, cj = cc - (cc/7)*7;
            int y  = (ci*16 + pi) * 2;
            int xx = (cj*16 + pj) * 2;
            const float* p = x + ((size_t)(b*3 + c)*224 + y)*224 + xx;
            float4 r0a = *reinterpret_cast<const float4*>(p);
            float4 r0b = *reinterpret_cast<const float4*>(p + 4);
            float4 r1a = *reinterpret_cast<const float4*>(p + 224);
            float4 r1b = *reinterpret_cast<const float4*>(p + 228);
            v0 = (r0a.x + r0a.y + r1a.x + r1a.y) * 0.25f;
            v1 = (r0a.z + r0a.w + r1a.z + r1a.w) * 0.25f;
            v2 = (r0b.x + r0b.y + r1b.x + r1b.y) * 0.25f;
            v3 = (r0b.z + r0b.w + r1b.z + r1b.w) * 0.25f;
        }
        __half2* dst = reinterpret_cast<__half2*>(&g_Ah[(size_t)row*KDIM + k4]);
        dst[0] = __floats2half2_rn(v0, v1);
        dst[1] = __floats2half2_rn(v2, v3);
    }
}

// ---------------- FP16 wmma GEMM, 3-stage pipeline, compact rows ----------------
#define TBM 128
#define TBN 128
#define TBK 64
#define NSTAGE 3
#define AS_STRIDE (TBK + 8)       // 72 halfs
#define BS_STRIDE (TBN + 8)       // 136 halfs
#define AS_HALFS (TBM*AS_STRIDE)             // 9216 per stage
#define BS_HALFS (TBK*BS_STRIDE)             // 8704 per stage
#define CS_STRIDE 132
#define STAGE_BYTES ((AS_HALFS + BS_HALFS)*2)                 // 35840
#define SMEM_BYTES_G ((NSTAGE*STAGE_BYTES) > (TBM*CS_STRIDE*4) ? (NSTAGE*STAGE_BYTES) : (TBM*CS_STRIDE*4))

__global__ void __launch_bounds__(256, 2) pe_gemm(
    const __half* __restrict__ Ah, const __half* __restrict__ Bh,
    const float* __restrict__ b_pe, const float* __restrict__ pos_fine,
    const float* __restrict__ pos_coarse, float* __restrict__ out,
    float* __restrict__ pe)
{
    const int M_dyn = g_nsel;
    int row0 = blockIdx.y * TBM;
    if (row0 >= M_dyn) return;

    extern __shared__ char smc[];
    __half* As = reinterpret_cast<__half*>(smc);                 // [NSTAGE][TBM][AS_STRIDE]
    __half* Bs = reinterpret_cast<__half*>(smc) + NSTAGE*AS_HALFS;

    const int N = CC, K = KDIM;
    int tid  = threadIdx.x;
    int warp = tid >> 5;
    int wr   = warp >> 1;     // 0..3 (32-row group)
    int wc   = warp & 1;      // 0..1 (64-col group)
    int col0 = blockIdx.x * TBN;

    int ar[4], ac8[4];
    bool avalid[4];
#pragma unroll
    for (int it = 0; it < 4; it++) {
        int lin = tid + it*256;
        ar[it]  = lin >> 3;              // 0..127
        ac8[it] = (lin & 7) << 3;        // 0..56 (halfs)
        avalid[it] = (row0 + ar[it]) < M_dyn;
    }
    int br[4], bc8[4];
#pragma unroll
    for (int it = 0; it < 4; it++) {
        int lin = tid + it*256;
        br[it]  = lin >> 4;              // 0..63
        bc8[it] = (lin & 15) << 3;       // 0..120 (halfs)
    }

    wmma::fragment<wmma::accumulator, 16, 16, 16, float> acc[2][4];
#pragma unroll
    for (int i = 0; i < 2; i++)
#pragma unroll
        for (int j = 0; j < 4; j++) wmma::fill_fragment(acc[i][j], 0.0f);

    auto load_stage = [&](int buf, int k0) {
        __half* Ab = As + buf*AS_HALFS;
        __half* Bb = Bs + buf*BS_HALFS;
#pragma unroll
        for (int it = 0; it < 4; it++) {
            const __half* src = Ah + (size_t)(row0 + ar[it])*K + k0 + ac8[it];
            cp_async16(smem_u32(&Ab[ar[it]*AS_STRIDE + ac8[it]]), src, avalid[it]);
        }
#pragma unroll
        for (int it = 0; it < 4; it++) {
            const __half* src = Bh + (size_t)(k0 + br[it])*N + col0 + bc8[it];
            cp_async16(smem_u32(&Bb[br[it]*BS_STRIDE + bc8[it]]), src, true);
        }
        cp_commit();
    };

    const int nK = K / TBK;   // 12
    load_stage(0, 0);
    load_stage(1, TBK);

    for (int kt = 0; kt < nK; kt++) {
        int buf = kt % NSTAGE;
        if (kt == nK - 1) cp_wait0(); else cp_wait1();   // stage kt complete
        __syncthreads();     // data visible + all warps done with stage kt-1 buffer
        if (kt + 2 < nK) load_stage((kt + 2) % NSTAGE, (kt + 2)*TBK);

        __half* Ab = As + buf*AS_HALFS;
        __half* Bb = Bs + buf*BS_HALFS;
#pragma unroll
        for (int kk = 0; kk < TBK; kk += 16) {
            wmma::fragment<wmma::matrix_a, 16, 16, 16, __half, wmma::row_major> af[2];
            wmma::fragment<wmma::matrix_b, 16, 16, 16, __half, wmma::row_major> bf[4];
#pragma unroll
            for (int i = 0; i < 2; i++)
                wmma::load_matrix_sync(af[i], &Ab[(wr*32 + i*16)*AS_STRIDE + kk], AS_STRIDE);
#pragma unroll
            for (int j = 0; j < 4; j++)
                wmma::load_matrix_sync(bf[j], &Bb[kk*BS_STRIDE + wc*64 + j*16], BS_STRIDE);
#pragma unroll
            for (int i = 0; i < 2; i++)
#pragma unroll
                for (int j = 0; j < 4; j++)
                    wmma::mma_sync(acc[i][j], af[i], bf[j], acc[i][j]);
        }
    }
    __syncthreads();

    // ---- fused epilogue: stage tile in smem, then scatter ----
    float* Cs = reinterpret_cast<float*>(smc);    // [TBM][CS_STRIDE]
#pragma unroll
    for (int i = 0; i < 2; i++)
#pragma unroll
        for (int j = 0; j < 4; j++)
            wmma::store_matrix_sync(&Cs[(wr*32 + i*16)*CS_STRIDE + wc*64 + j*16],
                                    acc[i][j], CS_STRIDE, wmma::mem_row_major);
    __syncthreads();

    int r    = tid >> 1;
    int half = tid & 1;
    int gm = row0 + r;
    if (gm >= M_dyn) return;
    int cbase = half*64;
    const float* srow = &Cs[r*CS_STRIDE + cbase];
    int dstrow = g_rowdst[gm];

    if (g_flag) {
        float* dst = pe + (size_t)dstrow*CC + col0 + cbase;
#pragma unroll
        for (int q = 0; q < 16; q++)
            *reinterpret_cast<float4*>(dst + q*4) =
                *reinterpret_cast<const float4*>(srow + q*4);
        return;
    }

    int emb = g_rowemb[gm];
    const float* etab = (emb < NFINE) ? (pos_fine + (size_t)emb*CC)
                                      : (pos_coarse + (size_t)(emb - NFINE)*CC);
    const float* bp = b_pe + col0 + cbase;
    const float* ep = etab + col0 + cbase;
    float* dst = out + (size_t)dstrow*CC + col0 + cbase;
#pragma unroll
    for (int q = 0; q < 16; q++) {
        float4 v = *reinterpret_cast<const float4*>(srow + q*4);
        float4 b = *reinterpret_cast<const float4*>(bp + q*4);
        float4 e = *reinterpret_cast<const float4*>(ep + q*4);
        *reinterpret_cast<float4*>(dst + q*4) =
            make_float4(v.x + b.x + e.x, v.y + b.y + e.y,
                        v.z + b.z + e.z, v.w + b.w + e.w);
    }
}

// ---------------- fp32 SGEMM, persistent (flag-guarded mini-attn path only) ----------------
#define BM 128
#define BN 128
#define BK 8
__global__ void __launch_bounds__(256) sgemm_bias(
    const float* __restrict__ A, const float* __restrict__ Bm,
    const float* __restrict__ bias, float* __restrict__ Cm,
    int M, int N, int K, const int* flagptr)
{
    if (flagptr && *flagptr == 0) return;
    __shared__ float As[BK][BM];
    __shared__ float Bs[BK][BN];
    int tid = threadIdx.x;
    int nx = N / BN;
    int ny = (M + BM - 1) / BM;
    int tx = tid & 15;
    int ty = tid >> 4;
    int aRow = tid >> 1;
    int aCol = (tid & 1) * 4;
    int bRow = tid >> 5;
    int bCol = (tid & 31) * 4;

    for (int tile = blockIdx.x; tile < nx*ny; tile += gridDim.x) {
        int row0 = (tile / nx) * BM;
        int col0 = (tile - (tile / nx)*nx) * BN;
        float acc[8][8];
#pragma unroll
        for (int i = 0; i < 8; i++)
#pragma unroll
            for (int j = 0; j < 8; j++) acc[i][j] = 0.0f;

        for (int k0 = 0; k0 < K; k0 += BK) {
            float4 av = make_float4(0.f, 0.f, 0.f, 0.f);
            int gm = row0 + aRow;
            if (gm < M) av = *reinterpret_cast<const float4*>(&A[(size_t)gm*K + k0 + aCol]);
            As[aCol+0][aRow] = av.x;
            As[aCol+1][aRow] = av.y;
            As[aCol+2][aRow] = av.z;
            As[aCol+3][aRow] = av.w;
            float4 bv = *reinterpret_cast<const float4*>(&Bm[(size_t)(k0 + bRow)*N + col0 + bCol]);
            *reinterpret_cast<float4*>(&Bs[bRow][bCol]) = bv;
            __syncthreads();
#pragma unroll
            for (int kk = 0; kk < BK; kk++) {
                float4 a0 = *reinterpret_cast<const float4*>(&As[kk][ty*8]);
                float4 a1 = *reinterpret_cast<const float4*>(&As[kk][ty*8+4]);
                float4 b0 = *reinterpret_cast<const float4*>(&Bs[kk][tx*8]);
                float4 b1 = *reinterpret_cast<const float4*>(&Bs[kk][tx*8+4]);
                float a[8] = {a0.x,a0.y,a0.z,a0.w,a1.x,a1.y,a1.z,a1.w};
                float b[8] = {b0.x,b0.y,b0.z,b0.w,b1.x,b1.y,b1.z,b1.w};
#pragma unroll
                for (int i = 0; i < 8; i++)
#pragma unroll
                    for (int j = 0; j < 8; j++) acc[i][j] += a[i] * b[j];
            }
            __syncthreads();
        }
        float4 bi0 = *reinterpret_cast<const float4*>(&bias[col0 + tx*8]);
        float4 bi1 = *reinterpret_cast<const float4*>(&bias[col0 + tx*8 + 4]);
#pragma unroll
        for (int i = 0; i < 8; i++) {
            int gm = row0 + ty*8 + i;
            if (gm < M) {
                float* cp = Cm + (size_t)gm*N + col0 + tx*8;
                float4 r0 = make_float4(acc[i][0]+bi0.x, acc[i][1]+bi0.y, acc[i][2]+bi0.z, acc[i][3]+bi0.w);
                float4 r1 = make_float4(acc[i][4]+bi1.x, acc[i][5]+bi1.y, acc[i][6]+bi1.z, acc[i][7]+bi1.w);
                *reinterpret_cast<float4*>(cp)     = r0;
                *reinterpret_cast<float4*>(cp + 4) = r1;
            }
        }
    }
}

// ---------------- mini-attention path (flag-guarded; dead when zero_w==0) ----------------
__global__ void __launch_bounds__(256) build_tok(const float* __restrict__ mini_pos,
                                                 const float* __restrict__ b_pe)
{
    if (g_flag == 0) return;
    for (int idx = blockIdx.x*blockDim.x + threadIdx.x; idx < BB*NCOARSE*4*CC;
         idx += gridDim.x*blockDim.x) {
        int c = idx % CC;
        int r = (idx / CC) & 3;
        int g = idx / (4*CC);
        int b = g / NCOARSE;
        int cc = g - b*NCOARSE;
        int ci = cc / 7, cj = cc - ci*7;
        int di = r >> 1, dj = r & 1;
        int f = (2*ci + di)*14 + (2*cj + dj);
        g_tok[idx] = g_pe[(size_t)(b*NFINE + f)*CC + c] + b_pe[c] + mini_pos[r*CC + c];
    }
}

__global__ void __launch_bounds__(128) mini_attn_kernel()
{
    if (g_flag == 0) return;
    __shared__ float q[4][CC];
    __shared__ float k[4][CC];
    __shared__ float att[4][4];
    int t = threadIdx.x;
    for (int g = blockIdx.x; g < BB*NCOARSE; g += gridDim.x) {
        if (!g_m32[g]) continue;
        for (int idx = t; idx < 4*CC; idx += 128) {
            int r = idx / CC, c = idx - r*CC;
            q[r][c] = g_qkv[(size_t)(g*4 + r)*N3 + c];
            k[r][c] = g_qkv[(size_t)(g*4 + r)*N3 + CC + c];
        }
        __syncthreads();
        if (t < 16) {
            int qr = t >> 2, kr = t & 3;
            float s = 0.f;
            for (int c = 0; c < CC; c++) s += q[qr][c] * k[kr][c];
            att[qr][kr] = s * rsqrtf((float)CC);
        }
        __syncthreads();
        if (t < 4) {
            float mx = att[t][0];
            for (int j = 1; j < 4; j++) mx = fmaxf(mx, att[t][j]);
            float e[4], sum = 0.f;
            for (int j = 0; j < 4; j++) { e[j] = __expf(att[t][j] - mx); sum += e[j]; }
            for (int j = 0; j < 4; j++) att[t][j] = e[j] / sum;
        }
        __syncthreads();
        for (int idx = t; idx < 4*CC; idx += 128) {
            int r = idx / CC, c = idx - r*CC;
            float s = 0.f;
            for (int kr = 0; kr < 4; kr++)
                s += att[r][kr] * g_qkv[(size_t)(g*4 + kr)*N3 + 2*CC + c];
            g_o[(size_t)(g*4 + r)*CC + c] = s;
        }
        __syncthreads();
    }
}

__global__ void __launch_bounds__(256) mean_kernel()
{
    if (g_flag == 0) return;
    for (int idx = blockIdx.x*blockDim.x + threadIdx.x; idx < BB*NCOARSE*CC;
         idx += gridDim.x*blockDim.x) {
        int g = idx / CC;
        int c = idx - g*CC;
        float s = 0.f;
        for (int r = 0; r < 4; r++) s += g_po[(size_t)(g*4 + r)*CC + c];
        g_mean[idx] = s * 0.25f;
    }
}

// ---------------- assemble (only used when g_flag != 0), persistent ----------------
__global__ void __launch_bounds__(256) assemble(
    const float* __restrict__ pos_fine, const float* __restrict__ pos_coarse,
    const float* __restrict__ b_pe, float* __restrict__ out)
{
    if (g_flag == 0) return;
    int t = threadIdx.x;
    for (int rid = blockIdx.x; rid < FINE_ROWS + COARSE_ROWS; rid += gridDim.x) {
        if (rid < FINE_ROWS) {
            int pos = g_finepos[rid];
            if (pos < 0) continue;
            int f = rid % NFINE;
            const float* src = g_pe + (size_t)rid*CC;
            const float* pe  = pos_fine + (size_t)f*CC;
            float* dst = out + (size_t)pos*CC;
            for (int c = t; c < CC; c += 256) dst[c] = src[c] + b_pe[c] + pe[c];
        } else {
            int r = rid - FINE_ROWS;
            int pos = g_coarsepos[r];
            if (pos < 0) continue;
            int cc = r % NCOARSE;
            const float* src = g_pe + (size_t)(FINE_ROWS + r)*CC;
            const float* pc  = pos_coarse + (size_t)cc*CC;
            const float* zz  = g_z + (size_t)r*CC;
            float* dst = out + (size_t)pos*CC;
            for (int c = t; c < CC; c += 256)
                dst[c] = src[c] + b_pe[c] + pc[c] + zz[c];
        }
    }
}

// ---------------- launch ----------------
template <typename T>
static void* sym_addr(const T& sym)
{
    void* p = nullptr;
    cudaGetSymbolAddress(&p, sym);
    return p;
}

extern "C" void kernel_launch(void* const* d_in, const int* in_sizes, int n_in,
                              void* d_out, int out_size)
{
    const float* x         = (const float*)d_in[0];
    const float* entropy   = (const float*)d_in[1];
    const float* W_pe      = (const float*)d_in[2];
    const float* b_pe      = (const float*)d_in[3];
    const float* qkv_w     = (const float*)d_in[4];
    const float* qkv_b     = (const float*)d_in[5];
    const float* proj_w    = (const float*)d_in[6];
    const float* proj_b    = (const float*)d_in[7];
    const float* mini_pos  = (const float*)d_in[8];
    const float* zero_w    = (const float*)d_in[9];
    const float* zero_b    = (const float*)d_in[10];
    const float* cls_token = (const float*)d_in[11];
    const float* pos_fine  = (const float*)d_in[12];
    const float* pos_coarse= (const float*)d_in[13];
    float* out = (float*)d_out;

    __half* p_Ah     = (__half*)sym_addr(g_Ah);
    __half* p_Wh     = (__half*)sym_addr(g_Wh);
    float* p_pe      = (float*)sym_addr(g_pe);
    float* p_tok     = (float*)sym_addr(g_tok);
    float* p_qkv     = (float*)sym_addr(g_qkv);
    float* p_o       = (float*)sym_addr(g_o);
    float* p_po      = (float*)sym_addr(g_po);
    float* p_mean    = (float*)sym_addr(g_mean);
    float* p_z       = (float*)sym_addr(g_z);
    int*   p_flag    = (int*)  sym_addr(g_flag);

    cudaFuncSetAttribute(pe_gemm, cudaFuncAttributeMaxDynamicSharedMemorySize, SMEM_BYTES_G);

    // 1: flag scan + W->fp16
    prep_kernel<<<576, 256>>>(zero_w, zero_b, W_pe);
    // 2: masks / compact maps
    mask_kernel<<<1, 128>>>(entropy, out, out_size);
    // 3: compact fp16 A build (fine gather + coarse mean) + cls rows
    build_A<<<1536, 256>>>(x, cls_token, mini_pos, out);
    // 4: compact fp16 patch-embed GEMM (3-stage pipeline), fused scatter epilogue
    pe_gemm<<<dim3(CC/TBN, (ALL_ROWS + TBM-1)/TBM), 256, SMEM_BYTES_G>>>(
        p_Ah, p_Wh, b_pe, pos_fine, pos_coarse, out, p_pe);

    // mini-attention residual path — dead when zero_w == 0 (persistent grids)
    const int MT = BB*NCOARSE*4;   // 12544
    build_tok<<<352, 256>>>(mini_pos, b_pe);
    sgemm_bias<<<296, 256>>>(p_tok, qkv_w, qkv_b, p_qkv, MT, N3, CC, p_flag);
    mini_attn_kernel<<<296, 128>>>();
    sgemm_bias<<<296, 256>>>(p_o, proj_w, proj_b, p_po, MT, CC, CC, p_flag);
    mean_kernel<<<296, 256>>>();
    sgemm_bias<<<296, 256>>>(p_mean, zero_w, zero_b, p_z, COARSE_ROWS, CC, CC, p_flag);

    // assemble (no-op unless zero_w/zero_b nonzero)
    assemble<<<592, 256>>>(pos_fine, pos_coarse, b_pe, out);
}

// round 13
// speedup vs baseline: 1.0736x; 1.0736x over previous
#include <cuda_runtime.h>
#include <cuda_fp16.h>
#include <cuda_bf16.h>
#include <mma.h>
#include <cstdint>

using namespace nvcuda;

// ---------------- problem constants ----------------
#define BB   64
#define CC   768
#define NFINE 196
#define NCOARSE 49
#define KDIM 768
#define N3   2304
#define FINE_ROWS   (BB*NFINE)     // 12544
#define COARSE_ROWS (BB*NCOARSE)   // 3136
#define ALL_ROWS    (FINE_ROWS + COARSE_ROWS)  // 15680

// ---------------- device scratch (static, no allocs) ----------------
__device__ __half g_Ah    [ALL_ROWS*KDIM];     // compact A rows in fp16
__device__ __half g_Wh    [KDIM*CC];           // W_pe in fp16
__device__ float g_pe     [ALL_ROWS*CC];       // only written when g_flag != 0
__device__ float g_tok    [BB*NCOARSE*4*CC];
__device__ float g_qkv    [BB*NCOARSE*4*N3];
__device__ float g_o      [BB*NCOARSE*4*CC];
__device__ float g_po     [BB*NCOARSE*4*CC];
__device__ float g_mean   [BB*NCOARSE*CC];
__device__ float g_z      [BB*NCOARSE*CC];
__device__ int   g_m32    [BB*NCOARSE];
__device__ int   g_finepos[BB*NFINE];
__device__ int   g_coarsepos[BB*NCOARSE];
__device__ int   g_rowsrc [ALL_ROWS];
__device__ int   g_rowdst [ALL_ROWS];
__device__ int   g_rowemb [ALL_ROWS];
__device__ int   g_nsel;
__device__ int   g_seq[BB];
__device__ int   g_cls[BB];
__device__ int   g_total;
__device__ int   g_flag;                        // monotone: set iff zero_w/zero_b nonzero

// ---------------- helpers ----------------
__device__ __forceinline__ uint32_t smem_u32(const void* p)
{
    uint32_t a;
    asm("{ .reg .u64 t; cvta.to.shared.u64 t, %1; cvt.u32.u64 %0, t; }" : "=r"(a) : "l"(p));
    return a;
}
__device__ __forceinline__ void cp_async16(uint32_t dst, const void* src, bool pred)
{
    int sz = pred ? 16 : 0;   // sz=0 -> zero-fill
    asm volatile("cp.async.cg.shared.global [%0], [%1], 16, %2;\n"
                 :: "r"(dst), "l"(src), "r"(sz));
}
__device__ __forceinline__ void cp_commit()  { asm volatile("cp.async.commit_group;\n"); }
__device__ __forceinline__ void cp_wait0()   { asm volatile("cp.async.wait_group 0;\n"); }

// ---------------- prep: flag scan + W_pe -> fp16 ----------------
__global__ void __launch_bounds__(256) prep_kernel(
    const float* __restrict__ zw, const float* __restrict__ zb,
    const float* __restrict__ W)
{
    int nz = 0;
    for (int i = blockIdx.x*blockDim.x + threadIdx.x; i < CC*CC; i += gridDim.x*blockDim.x) {
        nz |= (zw[i] != 0.0f);
        g_Wh[i] = __float2half_rn(W[i]);       // KDIM*CC == CC*CC
    }
    if (blockIdx.x == 0)
        for (int i = threadIdx.x; i < CC; i += blockDim.x) nz |= (zb[i] != 0.0f);
    if (__syncthreads_or(nz) && threadIdx.x == 0) atomicOr(&g_flag, 1);
}

// ---------------- mask / positions / compact row list ----------------
__global__ void __launch_bounds__(128) mask_kernel(
    const float* __restrict__ e, float* __restrict__ out, int out_size)
{
    __shared__ int s_nc[BB];
    __shared__ int s_cls[BB+1];
    __shared__ int s_flagv;
    int t = threadIdx.x;
    if (t == 0) s_flagv = g_flag;
    if (t < BB) {
        int b = t, nc = 0;
        const float* eb = e + b*NFINE;
        for (int cc = 0; cc < NCOARSE; cc++) {
            int ci = cc / 7, cj = cc % 7;
            float m = (eb[(2*ci)*14 + 2*cj]   + eb[(2*ci)*14 + 2*cj+1] +
                       eb[(2*ci+1)*14 + 2*cj] + eb[(2*ci+1)*14 + 2*cj+1]) * 0.25f;
            int sel = m < 0.5f;
            g_m32[b*NCOARSE + cc] = sel;
            nc += sel;
        }
        s_nc[t] = nc;
    }
    __syncthreads();
    if (t == 0) {
        int acc = 0;
        for (int b = 0; b < BB; b++) {
            s_cls[b] = acc;
            g_cls[b] = acc;
            int nc = s_nc[b];
            int seq = 1 + 4*(NCOARSE - nc) + nc;
            g_seq[b] = seq;
            acc += seq;
        }
        g_total = acc;
        s_cls[BB] = acc;
        g_nsel = s_flagv ? ALL_ROWS : (acc - BB);
    }
    __syncthreads();
    int flagv = s_flagv;
    if (t < BB) {
        int b = t;
        int base = s_cls[b];
        int idx  = base - b;
        int rank = 0;
        for (int f = 0; f < NFINE; f++) {
            int i = f / 14, j = f % 14;
            int sel = g_m32[b*NCOARSE + (i>>1)*7 + (j>>1)];
            int pos = sel ? -1 : (base + 1 + rank);
            g_finepos[b*NFINE + f] = pos;
            if (!sel) {
                if (!flagv) {
                    g_rowsrc[idx] = b*NFINE + f;
                    g_rowdst[idx] = pos;
                    g_rowemb[idx] = f;
                }
                idx++; rank++;
            }
        }
        int crank = 0;
        for (int cc = 0; cc < NCOARSE; cc++) {
            int sel = g_m32[b*NCOARSE + cc];
            int pos = sel ? (base + 1 + rank + crank) : -1;
            g_coarsepos[b*NCOARSE + cc] = pos;
            if (sel) {
                if (!flagv) {
                    g_rowsrc[idx] = FINE_ROWS + b*NCOARSE + cc;
                    g_rowdst[idx] = pos;
                    g_rowemb[idx] = NFINE + cc;
                }
                idx++; crank++;
            }
        }
    }
    if (flagv) {
        for (int i = t; i < ALL_ROWS; i += 128) { g_rowsrc[i] = i; g_rowdst[i] = i; }
    }
    __syncthreads();
    long long total = s_cls[BB];
    long long need = total * CC + 2*BB;
    if ((long long)out_size == need && t < BB) {
        out[total*CC + t]      = (float)g_seq[t];
        out[total*CC + BB + t] = (float)g_cls[t];
    }
}

// ---------------- build compact fp16 A matrix + cls rows ----------------
__global__ void __launch_bounds__(256) build_A(
    const float* __restrict__ x, const float* __restrict__ cls_token,
    const float* __restrict__ mini_pos, float* __restrict__ out)
{
    if (blockIdx.x < BB) {
        int pos = g_cls[blockIdx.x];
        float* dst = out + (size_t)pos*CC;
        for (int c = threadIdx.x; c < CC; c += 256) dst[c] = cls_token[c] + mini_pos[c];
    }
    int nsel = g_nsel;
    int total = nsel * (KDIM/4);                 // quads of 4 halfs
    for (int q = blockIdx.x*blockDim.x + threadIdx.x; q < total;
         q += gridDim.x*blockDim.x) {
        int row = q / (KDIM/4);
        int k4  = (q - row*(KDIM/4)) * 4;        // k of first element
        int src = g_rowsrc[row];
        float v0, v1, v2, v3;
        int c  = k4 >> 8;
        int pi = (k4 >> 4) & 15;
        int pj = k4 & 15;
        if (src < FINE_ROWS) {
            int b = src / NFINE;
            int f = src - b*NFINE;
            int i = f / 14, j = f - (f/14)*14;
            const float* p = x + ((size_t)(b*3 + c)*224 + i*16 + pi)*224 + j*16 + pj;
            float4 v = *reinterpret_cast<const float4*>(p);
            v0 = v.x; v1 = v.y; v2 = v.z; v3 = v.w;
        } else {
            int rr = src - FINE_ROWS;
            int b  = rr / NCOARSE;
            int cc = rr - b*NCOARSE;
            int ci = cc / 7, cj = cc - (cc/7)*7;
            int y  = (ci*16 + pi) * 2;
            int xx = (cj*16 + pj) * 2;
            const float* p = x + ((size_t)(b*3 + c)*224 + y)*224 + xx;
            float4 r0a = *reinterpret_cast<const float4*>(p);
            float4 r0b = *reinterpret_cast<const float4*>(p + 4);
            float4 r1a = *reinterpret_cast<const float4*>(p + 224);
            float4 r1b = *reinterpret_cast<const float4*>(p + 228);
            v0 = (r0a.x + r0a.y + r1a.x + r1a.y) * 0.25f;
            v1 = (r0a.z + r0a.w + r1a.z + r1a.w) * 0.25f;
            v2 = (r0b.x + r0b.y + r1b.x + r1b.y) * 0.25f;
            v3 = (r0b.z + r0b.w + r1b.z + r1b.w) * 0.25f;
        }
        __half2* dst = reinterpret_cast<__half2*>(&g_Ah[(size_t)row*KDIM + k4]);
        dst[0] = __floats2half2_rn(v0, v1);
        dst[1] = __floats2half2_rn(v2, v3);
    }
}

// ---------------- FP16 wmma GEMM, 2-stage, TBN=96 (wave balance) ----------------
#define TBM 128
#define TBN 96
#define TBK 64
#define AS_STRIDE (TBK + 8)       // 72 halfs
#define BS_STRIDE (TBN + 8)       // 104 halfs
#define AS_HALFS (TBM*AS_STRIDE)             // 9216 per stage
#define BS_HALFS (TBK*BS_STRIDE)             // 6656 per stage
#define CS_STRIDE 100
#define STAGE_BYTES ((AS_HALFS + BS_HALFS)*2)                 // 31744
#define SMEM_BYTES_G ((2*STAGE_BYTES) > (TBM*CS_STRIDE*4) ? (2*STAGE_BYTES) : (TBM*CS_STRIDE*4))

__global__ void __launch_bounds__(256, 2) pe_gemm(
    const __half* __restrict__ Ah, const __half* __restrict__ Bh,
    const float* __restrict__ b_pe, const float* __restrict__ pos_fine,
    const float* __restrict__ pos_coarse, float* __restrict__ out,
    float* __restrict__ pe)
{
    const int M_dyn = g_nsel;
    int row0 = blockIdx.y * TBM;
    if (row0 >= M_dyn) return;

    extern __shared__ char smc[];
    __half* As = reinterpret_cast<__half*>(smc);                 // [2][TBM][AS_STRIDE]
    __half* Bs = reinterpret_cast<__half*>(smc) + 2*AS_HALFS;    // [2][TBK][BS_STRIDE]

    const int N = CC, K = KDIM;
    int tid  = threadIdx.x;
    int warp = tid >> 5;
    int wr   = warp >> 1;     // 0..3 (32-row group)
    int wc   = warp & 1;      // 0..1 (48-col group)
    int col0 = blockIdx.x * TBN;

    // A loads: 128 rows x 8 chunks(16B=8 halfs) = 1024 / 256 thr = 4 slots
    int ar[4], ac8[4];
    bool avalid[4];
#pragma unroll
    for (int it = 0; it < 4; it++) {
        int lin = tid + it*256;
        ar[it]  = lin >> 3;              // 0..127
        ac8[it] = (lin & 7) << 3;        // 0..56 (halfs)
        avalid[it] = (row0 + ar[it]) < M_dyn;
    }
    // B loads: 64 rows x 12 chunks(8 halfs) = 768 / 256 thr = 3 slots
    int br[3], bc8[3];
#pragma unroll
    for (int it = 0; it < 3; it++) {
        int lin = tid + it*256;
        br[it]  = lin / 12;              // 0..63
        bc8[it] = (lin - br[it]*12) * 8; // 0..88 (halfs)
    }

    wmma::fragment<wmma::accumulator, 16, 16, 16, float> acc[2][3];
#pragma unroll
    for (int i = 0; i < 2; i++)
#pragma unroll
        for (int j = 0; j < 3; j++) wmma::fill_fragment(acc[i][j], 0.0f);

    auto load_stage = [&](int buf, int k0) {
        __half* Ab = As + buf*AS_HALFS;
        __half* Bb = Bs + buf*BS_HALFS;
#pragma unroll
        for (int it = 0; it < 4; it++) {
            const __half* src = Ah + (size_t)(row0 + ar[it])*K + k0 + ac8[it];
            cp_async16(smem_u32(&Ab[ar[it]*AS_STRIDE + ac8[it]]), src, avalid[it]);
        }
#pragma unroll
        for (int it = 0; it < 3; it++) {
            const __half* src = Bh + (size_t)(k0 + br[it])*N + col0 + bc8[it];
            cp_async16(smem_u32(&Bb[br[it]*BS_STRIDE + bc8[it]]), src, true);
        }
        cp_commit();
    };

    const int nK = K / TBK;   // 12
    load_stage(0, 0);

    for (int kt = 0; kt < nK; kt++) {
        int buf = kt & 1;
        cp_wait0();
        __syncthreads();
        if (kt + 1 < nK) load_stage(buf ^ 1, (kt + 1)*TBK);

        __half* Ab = As + buf*AS_HALFS;
        __half* Bb = Bs + buf*BS_HALFS;
#pragma unroll
        for (int kk = 0; kk < TBK; kk += 16) {
            wmma::fragment<wmma::matrix_a, 16, 16, 16, __half, wmma::row_major> af[2];
            wmma::fragment<wmma::matrix_b, 16, 16, 16, __half, wmma::row_major> bf[3];
#pragma unroll
            for (int i = 0; i < 2; i++)
                wmma::load_matrix_sync(af[i], &Ab[(wr*32 + i*16)*AS_STRIDE + kk], AS_STRIDE);
#pragma unroll
            for (int j = 0; j < 3; j++)
                wmma::load_matrix_sync(bf[j], &Bb[kk*BS_STRIDE + wc*48 + j*16], BS_STRIDE);
#pragma unroll
            for (int i = 0; i < 2; i++)
#pragma unroll
                for (int j = 0; j < 3; j++)
                    wmma::mma_sync(acc[i][j], af[i], bf[j], acc[i][j]);
        }
        __syncthreads();
    }

    // ---- fused epilogue: stage tile in smem, then scatter ----
    float* Cs = reinterpret_cast<float*>(smc);    // [TBM][CS_STRIDE]
#pragma unroll
    for (int i = 0; i < 2; i++)
#pragma unroll
        for (int j = 0; j < 3; j++)
            wmma::store_matrix_sync(&Cs[(wr*32 + i*16)*CS_STRIDE + wc*48 + j*16],
                                    acc[i][j], CS_STRIDE, wmma::mem_row_major);
    __syncthreads();

    int r    = tid >> 1;            // 0..127
    int half = tid & 1;             // 0..1 (48-col half)
    int gm = row0 + r;
    if (gm >= M_dyn) return;
    int cbase = half*48;
    const float* srow = &Cs[r*CS_STRIDE + cbase];
    int dstrow = g_rowdst[gm];

    if (g_flag) {
        float* dst = pe + (size_t)dstrow*CC + col0 + cbase;
#pragma unroll
        for (int q = 0; q < 12; q++)
            *reinterpret_cast<float4*>(dst + q*4) =
                *reinterpret_cast<const float4*>(srow + q*4);
        return;
    }

    int emb = g_rowemb[gm];
    const float* etab = (emb < NFINE) ? (pos_fine + (size_t)emb*CC)
                                      : (pos_coarse + (size_t)(emb - NFINE)*CC);
    const float* bp = b_pe + col0 + cbase;
    const float* ep = etab + col0 + cbase;
    float* dst = out + (size_t)dstrow*CC + col0 + cbase;
#pragma unroll
    for (int q = 0; q < 12; q++) {
        float4 v = *reinterpret_cast<const float4*>(srow + q*4);
        float4 b = *reinterpret_cast<const float4*>(bp + q*4);
        float4 e = *reinterpret_cast<const float4*>(ep + q*4);
        *reinterpret_cast<float4*>(dst + q*4) =
            make_float4(v.x + b.x + e.x, v.y + b.y + e.y,
                        v.z + b.z + e.z, v.w + b.w + e.w);
    }
}

// ---------------- fp32 SGEMM, persistent (flag-guarded mini-attn path only) ----------------
#define BM 128
#define BN 128
#define BK 8
__global__ void __launch_bounds__(256) sgemm_bias(
    const float* __restrict__ A, const float* __restrict__ Bm,
    const float* __restrict__ bias, float* __restrict__ Cm,
    int M, int N, int K, const int* flagptr)
{
    if (flagptr && *flagptr == 0) return;
    __shared__ float As[BK][BM];
    __shared__ float Bs[BK][BN];
    int tid = threadIdx.x;
    int nx = N / BN;
    int ny = (M + BM - 1) / BM;
    int tx = tid & 15;
    int ty = tid >> 4;
    int aRow = tid >> 1;
    int aCol = (tid & 1) * 4;
    int bRow = tid >> 5;
    int bCol = (tid & 31) * 4;

    for (int tile = blockIdx.x; tile < nx*ny; tile += gridDim.x) {
        int row0 = (tile / nx) * BM;
        int col0 = (tile - (tile / nx)*nx) * BN;
        float acc[8][8];
#pragma unroll
        for (int i = 0; i < 8; i++)
#pragma unroll
            for (int j = 0; j < 8; j++) acc[i][j] = 0.0f;

        for (int k0 = 0; k0 < K; k0 += BK) {
            float4 av = make_float4(0.f, 0.f, 0.f, 0.f);
            int gm = row0 + aRow;
            if (gm < M) av = *reinterpret_cast<const float4*>(&A[(size_t)gm*K + k0 + aCol]);
            As[aCol+0][aRow] = av.x;
            As[aCol+1][aRow] = av.y;
            As[aCol+2][aRow] = av.z;
            As[aCol+3][aRow] = av.w;
            float4 bv = *reinterpret_cast<const float4*>(&Bm[(size_t)(k0 + bRow)*N + col0 + bCol]);
            *reinterpret_cast<float4*>(&Bs[bRow][bCol]) = bv;
            __syncthreads();
#pragma unroll
            for (int kk = 0; kk < BK; kk++) {
                float4 a0 = *reinterpret_cast<const float4*>(&As[kk][ty*8]);
                float4 a1 = *reinterpret_cast<const float4*>(&As[kk][ty*8+4]);
                float4 b0 = *reinterpret_cast<const float4*>(&Bs[kk][tx*8]);
                float4 b1 = *reinterpret_cast<const float4*>(&Bs[kk][tx*8+4]);
                float a[8] = {a0.x,a0.y,a0.z,a0.w,a1.x,a1.y,a1.z,a1.w};
                float b[8] = {b0.x,b0.y,b0.z,b0.w,b1.x,b1.y,b1.z,b1.w};
#pragma unroll
                for (int i = 0; i < 8; i++)
#pragma unroll
                    for (int j = 0; j < 8; j++) acc[i][j] += a[i] * b[j];
            }
            __syncthreads();
        }
        float4 bi0 = *reinterpret_cast<const float4*>(&bias[col0 + tx*8]);
        float4 bi1 = *reinterpret_cast<const float4*>(&bias[col0 + tx*8 + 4]);
#pragma unroll
        for (int i = 0; i < 8; i++) {
            int gm = row0 + ty*8 + i;
            if (gm < M) {
                float* cp = Cm + (size_t)gm*N + col0 + tx*8;
                float4 r0 = make_float4(acc[i][0]+bi0.x, acc[i][1]+bi0.y, acc[i][2]+bi0.z, acc[i][3]+bi0.w);
                float4 r1 = make_float4(acc[i][4]+bi1.x, acc[i][5]+bi1.y, acc[i][6]+bi1.z, acc[i][7]+bi1.w);
                *reinterpret_cast<float4*>(cp)     = r0;
                *reinterpret_cast<float4*>(cp + 4) = r1;
            }
        }
    }
}

// ---------------- mini-attention path (flag-guarded; dead when zero_w==0) ----------------
__global__ void __launch_bounds__(256) build_tok(const float* __restrict__ mini_pos,
                                                 const float* __restrict__ b_pe)
{
    if (g_flag == 0) return;
    for (int idx = blockIdx.x*blockDim.x + threadIdx.x; idx < BB*NCOARSE*4*CC;
         idx += gridDim.x*blockDim.x) {
        int c = idx % CC;
        int r = (idx / CC) & 3;
        int g = idx / (4*CC);
        int b = g / NCOARSE;
        int cc = g - b*NCOARSE;
        int ci = cc / 7, cj = cc - ci*7;
        int di = r >> 1, dj = r & 1;
        int f = (2*ci + di)*14 + (2*cj + dj);
        g_tok[idx] = g_pe[(size_t)(b*NFINE + f)*CC + c] + b_pe[c] + mini_pos[r*CC + c];
    }
}

__global__ void __launch_bounds__(128) mini_attn_kernel()
{
    if (g_flag == 0) return;
    __shared__ float q[4][CC];
    __shared__ float k[4][CC];
    __shared__ float att[4][4];
    int t = threadIdx.x;
    for (int g = blockIdx.x; g < BB*NCOARSE; g += gridDim.x) {
        if (!g_m32[g]) continue;
        for (int idx = t; idx < 4*CC; idx += 128) {
            int r = idx / CC, c = idx - r*CC;
            q[r][c] = g_qkv[(size_t)(g*4 + r)*N3 + c];
            k[r][c] = g_qkv[(size_t)(g*4 + r)*N3 + CC + c];
        }
        __syncthreads();
        if (t < 16) {
            int qr = t >> 2, kr = t & 3;
            float s = 0.f;
            for (int c = 0; c < CC; c++) s += q[qr][c] * k[kr][c];
            att[qr][kr] = s * rsqrtf((float)CC);
        }
        __syncthreads();
        if (t < 4) {
            float mx = att[t][0];
            for (int j = 1; j < 4; j++) mx = fmaxf(mx, att[t][j]);
            float e[4], sum = 0.f;
            for (int j = 0; j < 4; j++) { e[j] = __expf(att[t][j] - mx); sum += e[j]; }
            for (int j = 0; j < 4; j++) att[t][j] = e[j] / sum;
        }
        __syncthreads();
        for (int idx = t; idx < 4*CC; idx += 128) {
            int r = idx / CC, c = idx - r*CC;
            float s = 0.f;
            for (int kr = 0; kr < 4; kr++)
                s += att[r][kr] * g_qkv[(size_t)(g*4 + kr)*N3 + 2*CC + c];
            g_o[(size_t)(g*4 + r)*CC + c] = s;
        }
        __syncthreads();
    }
}

__global__ void __launch_bounds__(256) mean_kernel()
{
    if (g_flag == 0) return;
    for (int idx = blockIdx.x*blockDim.x + threadIdx.x; idx < BB*NCOARSE*CC;
         idx += gridDim.x*blockDim.x) {
        int g = idx / CC;
        int c = idx - g*CC;
        float s = 0.f;
        for (int r = 0; r < 4; r++) s += g_po[(size_t)(g*4 + r)*CC + c];
        g_mean[idx] = s * 0.25f;
    }
}

// ---------------- assemble (only used when g_flag != 0), persistent ----------------
__global__ void __launch_bounds__(256) assemble(
    const float* __restrict__ pos_fine, const float* __restrict__ pos_coarse,
    const float* __restrict__ b_pe, float* __restrict__ out)
{
    if (g_flag == 0) return;
    int t = threadIdx.x;
    for (int rid = blockIdx.x; rid < FINE_ROWS + COARSE_ROWS; rid += gridDim.x) {
        if (rid < FINE_ROWS) {
            int pos = g_finepos[rid];
            if (pos < 0) continue;
            int f = rid % NFINE;
            const float* src = g_pe + (size_t)rid*CC;
            const float* pe  = pos_fine + (size_t)f*CC;
            float* dst = out + (size_t)pos*CC;
            for (int c = t; c < CC; c += 256) dst[c] = src[c] + b_pe[c] + pe[c];
        } else {
            int r = rid - FINE_ROWS;
            int pos = g_coarsepos[r];
            if (pos < 0) continue;
            int cc = r % NCOARSE;
            const float* src = g_pe + (size_t)(FINE_ROWS + r)*CC;
            const float* pc  = pos_coarse + (size_t)cc*CC;
            const float* zz  = g_z + (size_t)r*CC;
            float* dst = out + (size_t)pos*CC;
            for (int c = t; c < CC; c += 256)
                dst[c] = src[c] + b_pe[c] + pc[c] + zz[c];
        }
    }
}

// ---------------- launch ----------------
template <typename T>
static void* sym_addr(const T& sym)
{
    void* p = nullptr;
    cudaGetSymbolAddress(&p, sym);
    return p;
}

extern "C" void kernel_launch(void* const* d_in, const int* in_sizes, int n_in,
                              void* d_out, int out_size)
{
    const float* x         = (const float*)d_in[0];
    const float* entropy   = (const float*)d_in[1];
    const float* W_pe      = (const float*)d_in[2];
    const float* b_pe      = (const float*)d_in[3];
    const float* qkv_w     = (const float*)d_in[4];
    const float* qkv_b     = (const float*)d_in[5];
    const float* proj_w    = (const float*)d_in[6];
    const float* proj_b    = (const float*)d_in[7];
    const float* mini_pos  = (const float*)d_in[8];
    const float* zero_w    = (const float*)d_in[9];
    const float* zero_b    = (const float*)d_in[10];
    const float* cls_token = (const float*)d_in[11];
    const float* pos_fine  = (const float*)d_in[12];
    const float* pos_coarse= (const float*)d_in[13];
    float* out = (float*)d_out;

    __half* p_Ah     = (__half*)sym_addr(g_Ah);
    __half* p_Wh     = (__half*)sym_addr(g_Wh);
    float* p_pe      = (float*)sym_addr(g_pe);
    float* p_tok     = (float*)sym_addr(g_tok);
    float* p_qkv     = (float*)sym_addr(g_qkv);
    float* p_o       = (float*)sym_addr(g_o);
    float* p_po      = (float*)sym_addr(g_po);
    float* p_mean    = (float*)sym_addr(g_mean);
    float* p_z       = (float*)sym_addr(g_z);
    int*   p_flag    = (int*)  sym_addr(g_flag);

    cudaFuncSetAttribute(pe_gemm, cudaFuncAttributeMaxDynamicSharedMemorySize, SMEM_BYTES_G);

    // 1: flag scan + W->fp16
    prep_kernel<<<576, 256>>>(zero_w, zero_b, W_pe);
    // 2: masks / compact maps
    mask_kernel<<<1, 128>>>(entropy, out, out_size);
    // 3: compact fp16 A build (fine gather + coarse mean) + cls rows
    build_A<<<1536, 256>>>(x, cls_token, mini_pos, out);
    // 4: compact fp16 patch-embed GEMM (2-stage, TBN=96), fused scatter epilogue
    pe_gemm<<<dim3(CC/TBN, (ALL_ROWS + TBM-1)/TBM), 256, SMEM_BYTES_G>>>(
        p_Ah, p_Wh, b_pe, pos_fine, pos_coarse, out, p_pe);

    // mini-attention residual path — dead when zero_w == 0 (persistent grids)
    const int MT = BB*NCOARSE*4;   // 12544
    build_tok<<<352, 256>>>(mini_pos, b_pe);
    sgemm_bias<<<296, 256>>>(p_tok, qkv_w, qkv_b, p_qkv, MT, N3, CC, p_flag);
    mini_attn_kernel<<<296, 128>>>();
    sgemm_bias<<<296, 256>>>(p_o, proj_w, proj_b, p_po, MT, CC, CC, p_flag);
    mean_kernel<<<296, 256>>>();
    sgemm_bias<<<296, 256>>>(p_mean, zero_w, zero_b, p_z, COARSE_ROWS, CC, CC, p_flag);

    // assemble (no-op unless zero_w/zero_b nonzero)
    assemble<<<592, 256>>>(pos_fine, pos_coarse, b_pe, out);
}

// round 14
// speedup vs baseline: 1.1755x; 1.0949x over previous
#include <cuda_runtime.h>
#include <cuda_fp16.h>
#include <cuda_bf16.h>
#include <mma.h>
#include <cstdint>

using namespace nvcuda;

// ---------------- problem constants ----------------
#define BB   64
#define CC   768
#define NFINE 196
#define NCOARSE 49
#define KDIM 768
#define N3   2304
#define FINE_ROWS   (BB*NFINE)     // 12544
#define COARSE_ROWS (BB*NCOARSE)   // 3136
#define ALL_ROWS    (FINE_ROWS + COARSE_ROWS)  // 15680

// ---------------- device scratch (static, no allocs) ----------------
__device__ __half g_Ah    [ALL_ROWS*KDIM];
__device__ __half g_Wh    [KDIM*CC];
__device__ float g_pe     [ALL_ROWS*CC];       // only written when g_flag != 0
__device__ float g_tok    [BB*NCOARSE*4*CC];
__device__ float g_qkv    [BB*NCOARSE*4*N3];
__device__ float g_o      [BB*NCOARSE*4*CC];
__device__ float g_po     [BB*NCOARSE*4*CC];
__device__ float g_mean   [BB*NCOARSE*CC];
__device__ float g_z      [BB*NCOARSE*CC];
__device__ int   g_m32    [BB*NCOARSE];
__device__ int   g_finepos[BB*NFINE];
__device__ int   g_coarsepos[BB*NCOARSE];
__device__ int   g_rowsrc [ALL_ROWS];
__device__ int   g_rowdst [ALL_ROWS];
__device__ int   g_rowemb [ALL_ROWS];
__device__ int   g_nsel;                       // compact count (flag==0 meaning)
__device__ int   g_seq[BB];
__device__ int   g_cls[BB];
__device__ int   g_total;
__device__ int   g_flag;                        // monotone: set iff zero_w/zero_b nonzero
__device__ unsigned int g_gbar_cnt = 0;
__device__ unsigned int g_gbar_gen = 0;

// ---------------- helpers ----------------
__device__ __forceinline__ uint32_t smem_u32(const void* p)
{
    uint32_t a;
    asm("{ .reg .u64 t; cvta.to.shared.u64 t, %1; cvt.u32.u64 %0, t; }" : "=r"(a) : "l"(p));
    return a;
}
__device__ __forceinline__ void cp_async16(uint32_t dst, const void* src, bool pred)
{
    int sz = pred ? 16 : 0;
    asm volatile("cp.async.cg.shared.global [%0], [%1], 16, %2;\n"
                 :: "r"(dst), "l"(src), "r"(sz));
}
__device__ __forceinline__ void cp_commit()  { asm volatile("cp.async.commit_group;\n"); }
__device__ __forceinline__ void cp_wait0()   { asm volatile("cp.async.wait_group 0;\n"); }

// software grid barrier (all CTAs resident: grid=148, 1/SM)
__device__ void gbar()
{
    __syncthreads();
    if (threadIdx.x == 0) {
        __threadfence();
        unsigned int g = atomicAdd(&g_gbar_gen, 0u);
        unsigned int t = atomicAdd(&g_gbar_cnt, 1u);
        if (t == gridDim.x - 1) {
            g_gbar_cnt = 0;
            __threadfence();
            atomicAdd(&g_gbar_gen, 1u);
        } else {
            while (atomicAdd(&g_gbar_gen, 0u) == g) { __nanosleep(64); }
        }
    }
    __syncthreads();
}

// ---------------- prep (flag scan + W->fp16) + mask/compaction, merged ----------------
__global__ void __launch_bounds__(256) prep_mask(
    const float* __restrict__ zw, const float* __restrict__ zb,
    const float* __restrict__ W, const float* __restrict__ e,
    float* __restrict__ out, int out_size)
{
    int t = threadIdx.x;

    // ---- mask / compaction (last block only; independent of g_flag) ----
    if (blockIdx.x == gridDim.x - 1) {
        __shared__ int s_nc[BB];
        __shared__ int s_cls[BB+1];
        if (t < BB) {
            int b = t, nc = 0;
            const float* eb = e + b*NFINE;
            for (int cc = 0; cc < NCOARSE; cc++) {
                int ci = cc / 7, cj = cc % 7;
                float m = (eb[(2*ci)*14 + 2*cj]   + eb[(2*ci)*14 + 2*cj+1] +
                           eb[(2*ci+1)*14 + 2*cj] + eb[(2*ci+1)*14 + 2*cj+1]) * 0.25f;
                int sel = m < 0.5f;
                g_m32[b*NCOARSE + cc] = sel;
                nc += sel;
            }
            s_nc[t] = nc;
        }
        __syncthreads();
        if (t == 0) {
            int acc = 0;
            for (int b = 0; b < BB; b++) {
                s_cls[b] = acc;
                g_cls[b] = acc;
                int nc = s_nc[b];
                int seq = 1 + 4*(NCOARSE - nc) + nc;
                g_seq[b] = seq;
                acc += seq;
            }
            g_total = acc;
            s_cls[BB] = acc;
            g_nsel = acc - BB;      // compact count (flag==0 semantics)
        }
        __syncthreads();
        if (t < BB) {
            int b = t;
            int base = s_cls[b];
            int idx  = base - b;
            int rank = 0;
            for (int f = 0; f < NFINE; f++) {
                int i = f / 14, j = f % 14;
                int sel = g_m32[b*NCOARSE + (i>>1)*7 + (j>>1)];
                int pos = sel ? -1 : (base + 1 + rank);
                g_finepos[b*NFINE + f] = pos;
                if (!sel) {
                    g_rowsrc[idx] = b*NFINE + f;
                    g_rowdst[idx] = pos;
                    g_rowemb[idx] = f;
                    idx++; rank++;
                }
            }
            int crank = 0;
            for (int cc = 0; cc < NCOARSE; cc++) {
                int sel = g_m32[b*NCOARSE + cc];
                int pos = sel ? (base + 1 + rank + crank) : -1;
                g_coarsepos[b*NCOARSE + cc] = pos;
                if (sel) {
                    g_rowsrc[idx] = FINE_ROWS + b*NCOARSE + cc;
                    g_rowdst[idx] = pos;
                    g_rowemb[idx] = NFINE + cc;
                    idx++; crank++;
                }
            }
        }
        __syncthreads();
        long long total = s_cls[BB];
        long long need = total * CC + 2*BB;
        if ((long long)out_size == need && t < BB) {
            out[total*CC + t]      = (float)g_seq[t];
            out[total*CC + BB + t] = (float)g_cls[t];
        }
    }

    // ---- prep: flag scan + W_pe -> fp16 (all blocks) ----
    int nz = 0;
    for (int i = blockIdx.x*blockDim.x + t; i < CC*CC; i += gridDim.x*blockDim.x) {
        nz |= (zw[i] != 0.0f);
        g_Wh[i] = __float2half_rn(W[i]);
    }
    if (blockIdx.x == 0)
        for (int i = t; i < CC; i += blockDim.x) nz |= (zb[i] != 0.0f);
    if (__syncthreads_or(nz) && t == 0) atomicOr(&g_flag, 1);
}

// ---------------- build compact fp16 A matrix + cls rows ----------------
__global__ void __launch_bounds__(256) build_A(
    const float* __restrict__ x, const float* __restrict__ cls_token,
    const float* __restrict__ mini_pos, float* __restrict__ out)
{
    if (blockIdx.x < BB) {
        int pos = g_cls[blockIdx.x];
        float* dst = out + (size_t)pos*CC;
        for (int c = threadIdx.x; c < CC; c += 256) dst[c] = cls_token[c] + mini_pos[c];
    }
    int flagv = g_flag;
    int nsel = flagv ? ALL_ROWS : g_nsel;
    int total = nsel * (KDIM/4);
    for (int q = blockIdx.x*blockDim.x + threadIdx.x; q < total;
         q += gridDim.x*blockDim.x) {
        int row = q / (KDIM/4);
        int k4  = (q - row*(KDIM/4)) * 4;
        int src = flagv ? row : g_rowsrc[row];
        float v0, v1, v2, v3;
        int c  = k4 >> 8;
        int pi = (k4 >> 4) & 15;
        int pj = k4 & 15;
        if (src < FINE_ROWS) {
            int b = src / NFINE;
            int f = src - b*NFINE;
            int i = f / 14, j = f - (f/14)*14;
            const float* p = x + ((size_t)(b*3 + c)*224 + i*16 + pi)*224 + j*16 + pj;
            float4 v = *reinterpret_cast<const float4*>(p);
            v0 = v.x; v1 = v.y; v2 = v.z; v3 = v.w;
        } else {
            int rr = src - FINE_ROWS;
            int b  = rr / NCOARSE;
            int cc = rr - b*NCOARSE;
            int ci = cc / 7, cj = cc - (cc/7)*7;
            int y  = (ci*16 + pi) * 2;
            int xx = (cj*16 + pj) * 2;
            const float* p = x + ((size_t)(b*3 + c)*224 + y)*224 + xx;
            float4 r0a = *reinterpret_cast<const float4*>(p);
            float4 r0b = *reinterpret_cast<const float4*>(p + 4);
            float4 r1a = *reinterpret_cast<const float4*>(p + 224);
            float4 r1b = *reinterpret_cast<const float4*>(p + 228);
            v0 = (r0a.x + r0a.y + r1a.x + r1a.y) * 0.25f;
            v1 = (r0a.z + r0a.w + r1a.z + r1a.w) * 0.25f;
            v2 = (r0b.x + r0b.y + r1b.x + r1b.y) * 0.25f;
            v3 = (r0b.z + r0b.w + r1b.z + r1b.w) * 0.25f;
        }
        __half2* dst = reinterpret_cast<__half2*>(&g_Ah[(size_t)row*KDIM + k4]);
        dst[0] = __floats2half2_rn(v0, v1);
        dst[1] = __floats2half2_rn(v2, v3);
    }
}

// ---------------- FP16 wmma GEMM, 2-stage, TBN=96 ----------------
#define TBM 128
#define TBN 96
#define TBK 64
#define AS_STRIDE (TBK + 8)       // 72 halfs
#define BS_STRIDE (TBN + 8)       // 104 halfs
#define AS_HALFS (TBM*AS_STRIDE)
#define BS_HALFS (TBK*BS_STRIDE)
#define CS_STRIDE 100
#define STAGE_BYTES ((AS_HALFS + BS_HALFS)*2)
#define SMEM_BYTES_G ((2*STAGE_BYTES) > (TBM*CS_STRIDE*4) ? (2*STAGE_BYTES) : (TBM*CS_STRIDE*4))

__global__ void __launch_bounds__(256, 2) pe_gemm(
    const __half* __restrict__ Ah, const __half* __restrict__ Bh,
    const float* __restrict__ b_pe, const float* __restrict__ pos_fine,
    const float* __restrict__ pos_coarse, float* __restrict__ out,
    float* __restrict__ pe)
{
    int flagv = g_flag;
    const int M_dyn = flagv ? ALL_ROWS : g_nsel;
    int row0 = blockIdx.y * TBM;
    if (row0 >= M_dyn) return;

    extern __shared__ char smc[];
    __half* As = reinterpret_cast<__half*>(smc);
    __half* Bs = reinterpret_cast<__half*>(smc) + 2*AS_HALFS;

    const int N = CC, K = KDIM;
    int tid  = threadIdx.x;
    int warp = tid >> 5;
    int wr   = warp >> 1;
    int wc   = warp & 1;
    int col0 = blockIdx.x * TBN;

    int ar[4], ac8[4];
    bool avalid[4];
#pragma unroll
    for (int it = 0; it < 4; it++) {
        int lin = tid + it*256;
        ar[it]  = lin >> 3;
        ac8[it] = (lin & 7) << 3;
        avalid[it] = (row0 + ar[it]) < M_dyn;
    }
    int br[3], bc8[3];
#pragma unroll
    for (int it = 0; it < 3; it++) {
        int lin = tid + it*256;
        br[it]  = lin / 12;
        bc8[it] = (lin - br[it]*12) * 8;
    }

    wmma::fragment<wmma::accumulator, 16, 16, 16, float> acc[2][3];
#pragma unroll
    for (int i = 0; i < 2; i++)
#pragma unroll
        for (int j = 0; j < 3; j++) wmma::fill_fragment(acc[i][j], 0.0f);

    auto load_stage = [&](int buf, int k0) {
        __half* Ab = As + buf*AS_HALFS;
        __half* Bb = Bs + buf*BS_HALFS;
#pragma unroll
        for (int it = 0; it < 4; it++) {
            const __half* src = Ah + (size_t)(row0 + ar[it])*K + k0 + ac8[it];
            cp_async16(smem_u32(&Ab[ar[it]*AS_STRIDE + ac8[it]]), src, avalid[it]);
        }
#pragma unroll
        for (int it = 0; it < 3; it++) {
            const __half* src = Bh + (size_t)(k0 + br[it])*N + col0 + bc8[it];
            cp_async16(smem_u32(&Bb[br[it]*BS_STRIDE + bc8[it]]), src, true);
        }
        cp_commit();
    };

    const int nK = K / TBK;   // 12
    load_stage(0, 0);

    for (int kt = 0; kt < nK; kt++) {
        int buf = kt & 1;
        cp_wait0();
        __syncthreads();
        if (kt + 1 < nK) load_stage(buf ^ 1, (kt + 1)*TBK);

        __half* Ab = As + buf*AS_HALFS;
        __half* Bb = Bs + buf*BS_HALFS;
#pragma unroll
        for (int kk = 0; kk < TBK; kk += 16) {
            wmma::fragment<wmma::matrix_a, 16, 16, 16, __half, wmma::row_major> af[2];
            wmma::fragment<wmma::matrix_b, 16, 16, 16, __half, wmma::row_major> bf[3];
#pragma unroll
            for (int i = 0; i < 2; i++)
                wmma::load_matrix_sync(af[i], &Ab[(wr*32 + i*16)*AS_STRIDE + kk], AS_STRIDE);
#pragma unroll
            for (int j = 0; j < 3; j++)
                wmma::load_matrix_sync(bf[j], &Bb[kk*BS_STRIDE + wc*48 + j*16], BS_STRIDE);
#pragma unroll
            for (int i = 0; i < 2; i++)
#pragma unroll
                for (int j = 0; j < 3; j++)
                    wmma::mma_sync(acc[i][j], af[i], bf[j], acc[i][j]);
        }
        __syncthreads();
    }

    float* Cs = reinterpret_cast<float*>(smc);
#pragma unroll
    for (int i = 0; i < 2; i++)
#pragma unroll
        for (int j = 0; j < 3; j++)
            wmma::store_matrix_sync(&Cs[(wr*32 + i*16)*CS_STRIDE + wc*48 + j*16],
                                    acc[i][j], CS_STRIDE, wmma::mem_row_major);
    __syncthreads();

    int r    = tid >> 1;
    int half = tid & 1;
    int gm = row0 + r;
    if (gm >= M_dyn) return;
    int cbase = half*48;
    const float* srow = &Cs[r*CS_STRIDE + cbase];

    if (flagv) {
        float* dst = pe + (size_t)gm*CC + col0 + cbase;
#pragma unroll
        for (int q = 0; q < 12; q++)
            *reinterpret_cast<float4*>(dst + q*4) =
                *reinterpret_cast<const float4*>(srow + q*4);
        return;
    }

    int dstrow = g_rowdst[gm];
    int emb = g_rowemb[gm];
    const float* etab = (emb < NFINE) ? (pos_fine + (size_t)emb*CC)
                                      : (pos_coarse + (size_t)(emb - NFINE)*CC);
    const float* bp = b_pe + col0 + cbase;
    const float* ep = etab + col0 + cbase;
    float* dst = out + (size_t)dstrow*CC + col0 + cbase;
#pragma unroll
    for (int q = 0; q < 12; q++) {
        float4 v = *reinterpret_cast<const float4*>(srow + q*4);
        float4 b = *reinterpret_cast<const float4*>(bp + q*4);
        float4 e = *reinterpret_cast<const float4*>(ep + q*4);
        *reinterpret_cast<float4*>(dst + q*4) =
            make_float4(v.x + b.x + e.x, v.y + b.y + e.y,
                        v.z + b.z + e.z, v.w + b.w + e.w);
    }
}

// ---------------- fallback path devices (only run when g_flag != 0) ----------------
#define BM 128
#define BN 128
#define BK 8
__device__ void dev_sgemm(const float* __restrict__ A, const float* __restrict__ Bm,
                          const float* __restrict__ bias, float* __restrict__ Cm,
                          int M, int N, int K)
{
    __shared__ float As[BK][BM];
    __shared__ float Bs[BK][BN];
    int tid = threadIdx.x;
    int nx = N / BN;
    int ny = (M + BM - 1) / BM;
    int tx = tid & 15;
    int ty = tid >> 4;
    int aRow = tid >> 1;
    int aCol = (tid & 1) * 4;
    int bRow = tid >> 5;
    int bCol = (tid & 31) * 4;

    for (int tile = blockIdx.x; tile < nx*ny; tile += gridDim.x) {
        int row0 = (tile / nx) * BM;
        int col0 = (tile - (tile / nx)*nx) * BN;
        float acc[8][8];
#pragma unroll
        for (int i = 0; i < 8; i++)
#pragma unroll
            for (int j = 0; j < 8; j++) acc[i][j] = 0.0f;
        for (int k0 = 0; k0 < K; k0 += BK) {
            float4 av = make_float4(0.f, 0.f, 0.f, 0.f);
            int gm = row0 + aRow;
            if (gm < M) av = *reinterpret_cast<const float4*>(&A[(size_t)gm*K + k0 + aCol]);
            As[aCol+0][aRow] = av.x;
            As[aCol+1][aRow] = av.y;
            As[aCol+2][aRow] = av.z;
            As[aCol+3][aRow] = av.w;
            float4 bv = *reinterpret_cast<const float4*>(&Bm[(size_t)(k0 + bRow)*N + col0 + bCol]);
            *reinterpret_cast<float4*>(&Bs[bRow][bCol]) = bv;
            __syncthreads();
#pragma unroll
            for (int kk = 0; kk < BK; kk++) {
                float4 a0 = *reinterpret_cast<const float4*>(&As[kk][ty*8]);
                float4 a1 = *reinterpret_cast<const float4*>(&As[kk][ty*8+4]);
                float4 b0 = *reinterpret_cast<const float4*>(&Bs[kk][tx*8]);
                float4 b1 = *reinterpret_cast<const float4*>(&Bs[kk][tx*8+4]);
                float a[8] = {a0.x,a0.y,a0.z,a0.w,a1.x,a1.y,a1.z,a1.w};
                float b[8] = {b0.x,b0.y,b0.z,b0.w,b1.x,b1.y,b1.z,b1.w};
#pragma unroll
                for (int i = 0; i < 8; i++)
#pragma unroll
                    for (int j = 0; j < 8; j++) acc[i][j] += a[i] * b[j];
            }
            __syncthreads();
        }
        float4 bi0 = *reinterpret_cast<const float4*>(&bias[col0 + tx*8]);
        float4 bi1 = *reinterpret_cast<const float4*>(&bias[col0 + tx*8 + 4]);
#pragma unroll
        for (int i = 0; i < 8; i++) {
            int gm = row0 + ty*8 + i;
            if (gm < M) {
                float* cp = Cm + (size_t)gm*N + col0 + tx*8;
                float4 r0 = make_float4(acc[i][0]+bi0.x, acc[i][1]+bi0.y, acc[i][2]+bi0.z, acc[i][3]+bi0.w);
                float4 r1 = make_float4(acc[i][4]+bi1.x, acc[i][5]+bi1.y, acc[i][6]+bi1.z, acc[i][7]+bi1.w);
                *reinterpret_cast<float4*>(cp)     = r0;
                *reinterpret_cast<float4*>(cp + 4) = r1;
            }
        }
    }
}

__device__ void dev_mini_attn()
{
    __shared__ float q[4][CC];
    __shared__ float k[4][CC];
    __shared__ float att[4][4];
    int t = threadIdx.x;
    for (int g = blockIdx.x; g < BB*NCOARSE; g += gridDim.x) {
        if (!g_m32[g]) continue;
        for (int idx = t; idx < 4*CC; idx += blockDim.x) {
            int r = idx / CC, c = idx - r*CC;
            q[r][c] = g_qkv[(size_t)(g*4 + r)*N3 + c];
            k[r][c] = g_qkv[(size_t)(g*4 + r)*N3 + CC + c];
        }
        __syncthreads();
        if (t < 16) {
            int qr = t >> 2, kr = t & 3;
            float s = 0.f;
            for (int c = 0; c < CC; c++) s += q[qr][c] * k[kr][c];
            att[qr][kr] = s * rsqrtf((float)CC);
        }
        __syncthreads();
        if (t < 4) {
            float mx = att[t][0];
            for (int j = 1; j < 4; j++) mx = fmaxf(mx, att[t][j]);
            float e[4], sum = 0.f;
            for (int j = 0; j < 4; j++) { e[j] = __expf(att[t][j] - mx); sum += e[j]; }
            for (int j = 0; j < 4; j++) att[t][j] = e[j] / sum;
        }
        __syncthreads();
        for (int idx = t; idx < 4*CC; idx += blockDim.x) {
            int r = idx / CC, c = idx - r*CC;
            float s = 0.f;
            for (int kr = 0; kr < 4; kr++)
                s += att[r][kr] * g_qkv[(size_t)(g*4 + kr)*N3 + 2*CC + c];
            g_o[(size_t)(g*4 + r)*CC + c] = s;
        }
        __syncthreads();
    }
}

__global__ void __launch_bounds__(256) fallback_kernel(
    const float* __restrict__ mini_pos, const float* __restrict__ b_pe,
    const float* __restrict__ qkv_w, const float* __restrict__ qkv_b,
    const float* __restrict__ proj_w, const float* __restrict__ proj_b,
    const float* __restrict__ zero_w, const float* __restrict__ zero_b,
    const float* __restrict__ pos_fine, const float* __restrict__ pos_coarse,
    float* __restrict__ out)
{
    if (g_flag == 0) return;     // all blocks exit before any barrier
    const int MT = BB*NCOARSE*4;

    // P0: build tokens
    for (int idx = blockIdx.x*blockDim.x + threadIdx.x; idx < MT*CC;
         idx += gridDim.x*blockDim.x) {
        int c = idx % CC;
        int r = (idx / CC) & 3;
        int g = idx / (4*CC);
        int b = g / NCOARSE;
        int cc = g - b*NCOARSE;
        int ci = cc / 7, cj = cc - ci*7;
        int di = r >> 1, dj = r & 1;
        int f = (2*ci + di)*14 + (2*cj + dj);
        g_tok[idx] = g_pe[(size_t)(b*NFINE + f)*CC + c] + b_pe[c] + mini_pos[r*CC + c];
    }
    gbar();
    // P1: qkv gemm
    dev_sgemm(g_tok, qkv_w, qkv_b, g_qkv, MT, N3, CC);
    gbar();
    // P2: mini attention
    dev_mini_attn();
    gbar();
    // P3: proj gemm
    dev_sgemm(g_o, proj_w, proj_b, g_po, MT, CC, CC);
    gbar();
    // P4: mean over 4 tokens
    for (int idx = blockIdx.x*blockDim.x + threadIdx.x; idx < BB*NCOARSE*CC;
         idx += gridDim.x*blockDim.x) {
        int g = idx / CC;
        int c = idx - g*CC;
        float s = 0.f;
        for (int r = 0; r < 4; r++) s += g_po[(size_t)(g*4 + r)*CC + c];
        g_mean[idx] = s * 0.25f;
    }
    gbar();
    // P5: zero_conv gemm
    dev_sgemm(g_mean, zero_w, zero_b, g_z, COARSE_ROWS, CC, CC);
    gbar();
    // P6: assemble (fine + coarse rows from g_pe)
    int t = threadIdx.x;
    for (int rid = blockIdx.x; rid < FINE_ROWS + COARSE_ROWS; rid += gridDim.x) {
        if (rid < FINE_ROWS) {
            int pos = g_finepos[rid];
            if (pos < 0) continue;
            int f = rid % NFINE;
            const float* src = g_pe + (size_t)rid*CC;
            const float* pe  = pos_fine + (size_t)f*CC;
            float* dst = out + (size_t)pos*CC;
            for (int c = t; c < CC; c += blockDim.x) dst[c] = src[c] + b_pe[c] + pe[c];
        } else {
            int r = rid - FINE_ROWS;
            int pos = g_coarsepos[r];
            if (pos < 0) continue;
            int cc = r % NCOARSE;
            const float* src = g_pe + (size_t)(FINE_ROWS + r)*CC;
            const float* pc  = pos_coarse + (size_t)cc*CC;
            const float* zz  = g_z + (size_t)r*CC;
            float* dst = out + (size_t)pos*CC;
            for (int c = t; c < CC; c += blockDim.x)
                dst[c] = src[c] + b_pe[c] + pc[c] + zz[c];
        }
    }
}

// ---------------- launch ----------------
template <typename T>
static void* sym_addr(const T& sym)
{
    void* p = nullptr;
    cudaGetSymbolAddress(&p, sym);
    return p;
}

extern "C" void kernel_launch(void* const* d_in, const int* in_sizes, int n_in,
                              void* d_out, int out_size)
{
    const float* x         = (const float*)d_in[0];
    const float* entropy   = (const float*)d_in[1];
    const float* W_pe      = (const float*)d_in[2];
    const float* b_pe      = (const float*)d_in[3];
    const float* qkv_w     = (const float*)d_in[4];
    const float* qkv_b     = (const float*)d_in[5];
    const float* proj_w    = (const float*)d_in[6];
    const float* proj_b    = (const float*)d_in[7];
    const float* mini_pos  = (const float*)d_in[8];
    const float* zero_w    = (const float*)d_in[9];
    const float* zero_b    = (const float*)d_in[10];
    const float* cls_token = (const float*)d_in[11];
    const float* pos_fine  = (const float*)d_in[12];
    const float* pos_coarse= (const float*)d_in[13];
    float* out = (float*)d_out;

    __half* p_Ah     = (__half*)sym_addr(g_Ah);
    __half* p_Wh     = (__half*)sym_addr(g_Wh);
    float* p_pe      = (float*)sym_addr(g_pe);

    cudaFuncSetAttribute(pe_gemm, cudaFuncAttributeMaxDynamicSharedMemorySize, SMEM_BYTES_G);

    // 1: flag scan + W->fp16 + masks/compaction (merged)
    prep_mask<<<577, 256>>>(zero_w, zero_b, W_pe, entropy, out, out_size);
    // 2: compact fp16 A build + cls rows
    build_A<<<1536, 256>>>(x, cls_token, mini_pos, out);
    // 3: compact fp16 patch-embed GEMM, fused scatter epilogue
    pe_gemm<<<dim3(CC/TBN, (ALL_ROWS + TBM-1)/TBM), 256, SMEM_BYTES_G>>>(
        p_Ah, p_Wh, b_pe, pos_fine, pos_coarse, out, p_pe);
    // 4: single persistent fallback (entire mini-attn path; no-op when zero_w==0)
    fallback_kernel<<<148, 256>>>(mini_pos, b_pe, qkv_w, qkv_b, proj_w, proj_b,
                                  zero_w, zero_b, pos_fine, pos_coarse, out);
}